// round 8
// baseline (speedup 1.0000x reference)
#include <cuda_runtime.h>
#include <cuda_bf16.h>
#include <cstdint>

#define TT 512
#define BB 64
#define HH 512
#define MM (TT * BB)        // 32768
#define NN (4 * HH)         // 2048

typedef unsigned long long ull;

// ---------------- device scratch (static) ----------------
__device__ float g_zx[(size_t)MM * NN];             // 256 MB, [m][n]
__device__ __nv_bfloat16 g_xhi[(size_t)MM * HH];    // 32 MB
__device__ __nv_bfloat16 g_xlo[(size_t)MM * HH];    // 32 MB
__device__ __nv_bfloat16 g_whi[(size_t)HH * NN];    // 2 MB
__device__ __nv_bfloat16 g_wlo[(size_t)HH * NN];    // 2 MB
__device__ __nv_bfloat16 g_hb[2][2][BB * HH];       // h bf16 planes [buf][hi/lo][b][k]
__device__ int g_flag[128 * 32];                    // per-CTA epoch flags, 128B stride
__device__ int g_r_u8;

// ---------------- helpers ----------------
static __device__ __forceinline__ float sigf(float x) { return 1.0f / (1.0f + __expf(-x)); }
static __device__ __forceinline__ float clampf1(float x) { return fminf(fmaxf(x, -1.0f), 1.0f); }
static __device__ __forceinline__ unsigned packbf(float a, float b) {
    __nv_bfloat162 t = __floats2bfloat162_rn(a, b);
    return *(unsigned*)&t;
}
static __device__ __forceinline__ int ld_acq(const int* p) {
    int v;
    asm volatile("ld.acquire.gpu.global.b32 %0,[%1];" : "=r"(v) : "l"(p) : "memory");
    return v;
}
static __device__ __forceinline__ void st_rel(int* p, int v) {
    asm volatile("st.release.gpu.global.b32 [%0],%1;" :: "l"(p), "r"(v) : "memory");
}

static __device__ __forceinline__ void cpa16(uint32_t dst, const void* src) {
    asm volatile("cp.async.cg.shared.global [%0],[%1],16;\n" :: "r"(dst), "l"(src));
}
#define LDSM4(R, addr) \
    asm volatile("ldmatrix.sync.aligned.m8n8.x4.shared.b16 {%0,%1,%2,%3},[%4];" \
        : "=r"((R)[0]), "=r"((R)[1]), "=r"((R)[2]), "=r"((R)[3]) : "r"(addr))
#define LDSM2T(R, addr) \
    asm volatile("ldmatrix.sync.aligned.m8n8.x2.trans.shared.b16 {%0,%1},[%2];" \
        : "=r"((R)[0]), "=r"((R)[1]) : "r"(addr))
#define MMA_BF16(C, A, B) \
    asm volatile("mma.sync.aligned.m16n8k16.row.col.f32.bf16.bf16.f32 " \
        "{%0,%1,%2,%3},{%4,%5,%6,%7},{%8,%9},{%0,%1,%2,%3};" \
        : "+f"((C)[0]), "+f"((C)[1]), "+f"((C)[2]), "+f"((C)[3]) \
        : "r"((A)[0]), "r"((A)[1]), "r"((A)[2]), "r"((A)[3]), "r"((B)[0]), "r"((B)[1]))

// ---------------- kernel: reset-dtype detection + flag reset ----------------
__global__ void k_detect(const unsigned char* __restrict__ r) {
    __shared__ int nz;
    if (threadIdx.x == 0) nz = 0;
    __syncthreads();
    for (int i = threadIdx.x; i < 128 * 32; i += blockDim.x) g_flag[i] = 0;
    int loc = 0;
    for (int i = threadIdx.x; i < TT * BB; i += blockDim.x)
        if ((i & 3) && r[i]) loc = 1;
    if (loc) atomicOr(&nz, 1);
    __syncthreads();
    if (threadIdx.x == 0) g_r_u8 = nz;
}

// ---------------- conversion kernels ----------------
__global__ void k_convert_x(const float* __restrict__ xs) {
    size_t i0 = ((size_t)blockIdx.x * blockDim.x + threadIdx.x) * 4;
    #pragma unroll
    for (int u = 0; u < 4; ++u) {
        size_t i = i0 + u;
        if (i < (size_t)MM * HH) {
            float v = xs[i];
            __nv_bfloat16 hi = __float2bfloat16(v);
            g_xhi[i] = hi;
            g_xlo[i] = __float2bfloat16(v - __bfloat162float(hi));
        }
    }
}
__global__ void k_convert_w(const float* __restrict__ Wi) {
    size_t i0 = ((size_t)blockIdx.x * blockDim.x + threadIdx.x) * 4;
    #pragma unroll
    for (int u = 0; u < 4; ++u) {
        size_t i = i0 + u;
        if (i < (size_t)HH * NN) {
            float v = Wi[i];
            __nv_bfloat16 hi = __float2bfloat16(v);
            g_whi[i] = hi;
            g_wlo[i] = __float2bfloat16(v - __bfloat162float(hi));
        }
    }
}

// ---------------- kernel: h init (bf16 hi/lo planes, [b][k]) ----------------
__global__ void k_hinit(const float* __restrict__ h0, const void* __restrict__ resets) {
    const int ru8 = g_r_u8;
    const unsigned char* r8 = (const unsigned char*)resets;
    const int* r32 = (const int*)resets;
    for (int idx = threadIdx.x + blockIdx.x * blockDim.x; idx < HH * BB;
         idx += blockDim.x * gridDim.x) {
        int b = idx >> 9, k = idx & 511;
        bool rs = ru8 ? (r8[b] != 0) : (r32[b] != 0);
        float hv = rs ? 0.0f : h0[b * HH + k];
        __nv_bfloat16 hi = __float2bfloat16(hv);
        g_hb[0][0][idx] = hi;
        g_hb[0][1][idx] = __float2bfloat16(hv - __bfloat162float(hi));
    }
}

// ---------------- kernel: zx = x @ Wi  (bf16 3-split tensor-core GEMM) ----------------
#define AROW 24
#define BROW 136

#define LOAD_STAGE(buf, ks) do {                                                           \
    const int kb_ = (ks) * 16;                                                             \
    _Pragma("unroll")                                                                      \
    for (int j_ = 0; j_ < 4; ++j_) {                                                       \
        int id_ = tid + 256 * j_;                                                          \
        if (id_ < 512) {                                                                   \
            int plane_ = id_ >> 8; int r_ = id_ & 255; int row_ = r_ >> 1; int half_ = r_ & 1; \
            const __nv_bfloat16* src_ = (plane_ ? g_xlo : g_xhi)                           \
                + (size_t)(mbase + row_) * HH + kb_ + half_ * 8;                           \
            uint32_t dst_ = Abase + (((buf) * 2 + plane_) * 128 * AROW + row_ * AROW + half_ * 8) * 2; \
            cpa16(dst_, src_);                                                             \
        } else {                                                                           \
            int id2_ = id_ - 512; int plane_ = id2_ >> 8; int r_ = id2_ & 255;             \
            int krow_ = r_ >> 4; int seg_ = r_ & 15;                                       \
            const __nv_bfloat16* src_ = (plane_ ? g_wlo : g_whi)                           \
                + (size_t)(kb_ + krow_) * NN + nbase + seg_ * 8;                           \
            uint32_t dst_ = Bbase + (((buf) * 2 + plane_) * 16 * BROW + krow_ * BROW + seg_ * 8) * 2; \
            cpa16(dst_, src_);                                                             \
        }                                                                                  \
    } } while (0)

__global__ __launch_bounds__(256) void k_mm_pre() {
    __shared__ __align__(128) __nv_bfloat16 Asm[2][2][128 * AROW];
    __shared__ __align__(128) __nv_bfloat16 Bsm[2][2][16 * BROW];
    const int tid = threadIdx.x;
    const int nbase = blockIdx.x * 128;
    const int mbase = blockIdx.y * 128;
    const int wid = tid >> 5, lane = tid & 31;
    const int wm = wid & 1, wn = wid >> 1;

    uint32_t Abase = (uint32_t)__cvta_generic_to_shared(&Asm[0][0][0]);
    uint32_t Bbase = (uint32_t)__cvta_generic_to_shared(&Bsm[0][0][0]);

    const int gid = lane >> 2, tig = lane & 3;
    const int arow = (lane & 7) + 8 * ((lane >> 3) & 1);
    const int acol = (lane >> 4) * 8;
    const int bk = lane & 15;

    float c[4][4][4] = {};

    LOAD_STAGE(0, 0);
    asm volatile("cp.async.commit_group;\n");

    #pragma unroll 1
    for (int ks = 0; ks < 32; ++ks) {
        const int buf = ks & 1;
        if (ks < 31) {
            LOAD_STAGE((ks + 1) & 1, ks + 1);
            asm volatile("cp.async.commit_group;\n");
            asm volatile("cp.async.wait_group 1;\n");
        } else {
            asm volatile("cp.async.wait_group 0;\n");
        }
        __syncthreads();

        uint32_t a_hi[4][4], a_lo[4][4];
        #pragma unroll
        for (int mi = 0; mi < 4; ++mi) {
            int rowoff = wm * 64 + mi * 16 + arow;
            uint32_t ah = Abase + ((buf * 2 + 0) * 128 * AROW + rowoff * AROW + acol) * 2;
            uint32_t al = Abase + ((buf * 2 + 1) * 128 * AROW + rowoff * AROW + acol) * 2;
            LDSM4(a_hi[mi], ah);
            LDSM4(a_lo[mi], al);
        }
        uint32_t bhf[4][2], blf[4][2];
        #pragma unroll
        for (int ni = 0; ni < 4; ++ni) {
            int n0 = wn * 32 + ni * 8;
            uint32_t bh = Bbase + ((buf * 2 + 0) * 16 * BROW + bk * BROW + n0) * 2;
            uint32_t bl = Bbase + ((buf * 2 + 1) * 16 * BROW + bk * BROW + n0) * 2;
            LDSM2T(bhf[ni], bh);
            LDSM2T(blf[ni], bl);
        }
        #pragma unroll
        for (int mi = 0; mi < 4; ++mi)
            #pragma unroll
            for (int ni = 0; ni < 4; ++ni) {
                MMA_BF16(c[mi][ni], a_hi[mi], bhf[ni]);
                MMA_BF16(c[mi][ni], a_hi[mi], blf[ni]);
                MMA_BF16(c[mi][ni], a_lo[mi], bhf[ni]);
            }
        __syncthreads();
    }

    #pragma unroll
    for (int mi = 0; mi < 4; ++mi)
        #pragma unroll
        for (int ni = 0; ni < 4; ++ni) {
            int m0 = mbase + wm * 64 + mi * 16 + gid;
            int n = nbase + wn * 32 + ni * 8 + tig * 2;
            *(float2*)(g_zx + (size_t)m0 * NN + n) = make_float2(c[mi][ni][0], c[mi][ni][1]);
            *(float2*)(g_zx + (size_t)(m0 + 8) * NN + n) = make_float2(c[mi][ni][2], c[mi][ni][3]);
        }
}

// ---------------- kernel: persistent scanned-LSTM (tensor-core h @ Wh) ----------------
// 128 CTAs x 256 threads. CTA owns 16 z-cols: col(l) = (l>>2)*512 + cta*4 + (l&3).
// Warps K-split: warp w owns k in [64w, 64w+64)  -> depends only on CTAs 16w..16w+16.
// Per-CTA epoch flags; warps spin (lane-parallel acquire loads) on their 16 producers.
#define ZP 18

__global__ __launch_bounds__(256, 1)
void lstm_main(const float* __restrict__ Wh, const float* __restrict__ bias,
               const float* __restrict__ c0, const void* __restrict__ resets,
               float* __restrict__ ys) {
    __shared__ float zs[8][64][ZP];   // 36,864 B

    const int tid = threadIdx.x;
    const int cta = blockIdx.x;
    const int wid = tid >> 5, lane = tid & 31;
    const int gid = lane >> 2, tig = lane & 3;
    const int wk = wid * 64;

    // this warp's producer flag (one of the 16 CTAs owning our k-slice)
    const int* myflag = g_flag + ((wid * 16 + (lane & 15)) << 5);

    // ---- build register-resident B fragments from fp32 Wh (once) ----
    unsigned bh[2][4][2], bl[2][4][2];
    #pragma unroll
    for (int nt = 0; nt < 2; ++nt) {
        const int l = nt * 8 + gid;
        const int gcol = (l >> 2) * 512 + cta * 4 + (l & 3);
        #pragma unroll
        for (int kt = 0; kt < 4; ++kt) {
            const int k0 = wk + kt * 16 + 2 * tig;
            float f0 = Wh[(size_t)k0 * NN + gcol];
            float f1 = Wh[(size_t)(k0 + 1) * NN + gcol];
            float f2 = Wh[(size_t)(k0 + 8) * NN + gcol];
            float f3 = Wh[(size_t)(k0 + 9) * NN + gcol];
            float h0f = __bfloat162float(__float2bfloat16(f0));
            float h1f = __bfloat162float(__float2bfloat16(f1));
            float h2f = __bfloat162float(__float2bfloat16(f2));
            float h3f = __bfloat162float(__float2bfloat16(f3));
            bh[nt][kt][0] = packbf(h0f, h1f);
            bh[nt][kt][1] = packbf(h2f, h3f);
            bl[nt][kt][0] = packbf(f0 - h0f, f1 - h1f);
            bl[nt][kt][1] = packbf(f2 - h2f, f3 - h3f);
        }
    }

    // ---- epilogue identity: one (b, j) element ----
    const int eb = tid >> 2;
    const int ej = tid & 3;
    const int jcol = cta * 4 + ej;
    float c = c0[eb * HH + jcol];
    const float bi = bias[jcol];
    const float bf = bias[512 + jcol];
    const float bg = bias[1024 + jcol];
    const float bo = bias[1536 + jcol];
    const int ru8 = g_r_u8;
    const unsigned char* r8 = (const unsigned char*)resets;
    const int* r32 = (const int*)resets;

    int* ctaflag = g_flag + (cta << 5);

    for (int t = 0; t < TT; ++t) {
        // zx prefetch (DRAM) — issue BEFORE the flag wait so latency hides under it
        const float* zxr = g_zx + (size_t)(t * BB + eb) * NN + jcol;
        float z0 = __ldcg(zxr);
        float z1 = __ldcg(zxr + 512);
        float z2 = __ldcg(zxr + 1024);
        float z3 = __ldcg(zxr + 1536);

        // ---- dependency wait: this warp's 16 producers must have published h[t] ----
        if (t > 0) {
            unsigned ok;
            do {
                int v = ld_acq(myflag);
                ok = __ballot_sync(0xffffffffu, v >= t);
            } while (ok != 0xffffffffu);
        }

        const __nv_bfloat16* hhi = g_hb[t & 1][0];
        const __nv_bfloat16* hlo = g_hb[t & 1][1];

        float acc[4][2][4];
        #pragma unroll
        for (int mt = 0; mt < 4; ++mt)
            #pragma unroll
            for (int nt = 0; nt < 2; ++nt)
                #pragma unroll
                for (int q = 0; q < 4; ++q) acc[mt][nt][q] = 0.0f;

        #pragma unroll
        for (int kt = 0; kt < 4; ++kt) {
            unsigned ahi[4][4], alo[4][4];
            #pragma unroll
            for (int mt = 0; mt < 4; ++mt) {
                const int r0 = mt * 16 + gid;
                const int k0 = wk + kt * 16 + 2 * tig;
                const unsigned* ph  = (const unsigned*)(hhi + r0 * HH + k0);
                const unsigned* ph8 = (const unsigned*)(hhi + (r0 + 8) * HH + k0);
                const unsigned* pl  = (const unsigned*)(hlo + r0 * HH + k0);
                const unsigned* pl8 = (const unsigned*)(hlo + (r0 + 8) * HH + k0);
                ahi[mt][0] = __ldcg(ph);
                ahi[mt][1] = __ldcg(ph8);
                ahi[mt][2] = __ldcg(ph + 4);
                ahi[mt][3] = __ldcg(ph8 + 4);
                alo[mt][0] = __ldcg(pl);
                alo[mt][1] = __ldcg(pl8);
                alo[mt][2] = __ldcg(pl + 4);
                alo[mt][3] = __ldcg(pl8 + 4);
            }
            #pragma unroll
            for (int mt = 0; mt < 4; ++mt)
                #pragma unroll
                for (int nt = 0; nt < 2; ++nt) {
                    MMA_BF16(acc[mt][nt], ahi[mt], bh[nt][kt]);
                    MMA_BF16(acc[mt][nt], ahi[mt], bl[nt][kt]);
                    MMA_BF16(acc[mt][nt], alo[mt], bh[nt][kt]);
                }
        }

        // write K-split partials
        #pragma unroll
        for (int mt = 0; mt < 4; ++mt)
            #pragma unroll
            for (int nt = 0; nt < 2; ++nt) {
                const int r0 = mt * 16 + gid;
                const int col = nt * 8 + 2 * tig;
                *(float2*)&zs[wid][r0][col]     = make_float2(acc[mt][nt][0], acc[mt][nt][1]);
                *(float2*)&zs[wid][r0 + 8][col] = make_float2(acc[mt][nt][2], acc[mt][nt][3]);
            }
        __syncthreads();

        // ---- epilogue ----
        {
            float zi = z0 + bi, zf = z1 + bf, zg = z2 + bg, zo = z3 + bo;
            #pragma unroll
            for (int s = 0; s < 8; ++s) {
                const float* zr = zs[s][eb];
                zi += zr[ej];
                zf += zr[4 + ej];
                zg += zr[8 + ej];
                zo += zr[12 + ej];
            }

            bool rs = ru8 ? (r8[t * BB + eb] != 0) : (r32[t * BB + eb] != 0);
            if (rs) c = 0.0f;

            float iv = sigf(zi);
            float fv = sigf(zf);
            float gv = tanhf(zg);
            float ov = sigf(zo);
            float ncr = fv * c + iv * gv;
            float nh = ov * tanhf(ncr);
            c = clampf1(ncr);
            float nhc = clampf1(nh);

            ys[(size_t)t * BB * HH + (size_t)eb * HH + jcol] = nhc;
            if (t + 1 < TT) {
                bool rs2 = ru8 ? (r8[(t + 1) * BB + eb] != 0) : (r32[(t + 1) * BB + eb] != 0);
                float hv = rs2 ? 0.0f : nhc;
                __nv_bfloat16 hi = __float2bfloat16(hv);
                const int nb = (t + 1) & 1;
                g_hb[nb][0][eb * HH + jcol] = hi;
                g_hb[nb][1][eb * HH + jcol] = __float2bfloat16(hv - __bfloat162float(hi));
            }
        }

        // ---- publish: all our h stores done -> release our epoch flag ----
        __syncthreads();
        if (tid == 0) {
            __threadfence();
            st_rel(ctaflag, t + 1);
        }
    }
}

// ---------------- launch ----------------
extern "C" void kernel_launch(void* const* d_in, const int* in_sizes, int n_in,
                              void* d_out, int out_size) {
    const float* xs     = (const float*)d_in[0];
    const void*  resets = d_in[1];
    const float* c0     = (const float*)d_in[2];
    const float* h0     = (const float*)d_in[3];
    const float* Wi     = (const float*)d_in[4];
    const float* Wh     = (const float*)d_in[5];
    const float* bias   = (const float*)d_in[6];
    float* ys = (float*)d_out;

    k_detect<<<1, 256>>>((const unsigned char*)resets);
    k_convert_x<<<16384, 256>>>(xs);
    k_convert_w<<<1024, 256>>>(Wi);
    k_hinit<<<32, 256>>>(h0, resets);
    dim3 gpre(16, 256);
    k_mm_pre<<<gpre, 256>>>();
    lstm_main<<<128, 256>>>(Wh, bias, c0, resets, ys);
}

// round 14
// speedup vs baseline: 1.3027x; 1.3027x over previous
#include <cuda_runtime.h>
#include <cuda_bf16.h>
#include <cstdint>

#define TT 512
#define BB 64
#define HH 512
#define MM (TT * BB)        // 32768
#define NN (4 * HH)         // 2048

// ---------------- device scratch (static) ----------------
__device__ float g_zx[(size_t)MM * NN];                       // 256 MB, [m][n]
__device__ __nv_bfloat16 g_xhi[(size_t)MM * HH];              // 32 MB
__device__ __nv_bfloat16 g_xlo[(size_t)MM * HH];              // 32 MB
__device__ __nv_bfloat16 g_whi[(size_t)HH * NN];              // 2 MB
__device__ __nv_bfloat16 g_wlo[(size_t)HH * NN];              // 2 MB
__device__ __align__(128) __nv_bfloat16 g_hb[2][2][BB * HH];  // h bf16 planes [buf][hi/lo][b][k]
__device__ int g_flag[128 * 32];                              // per-CTA epoch flags, 128B stride
__device__ int g_r_u8;

// ---------------- helpers ----------------
static __device__ __forceinline__ float sigf(float x) { return 1.0f / (1.0f + __expf(-x)); }
static __device__ __forceinline__ float clampf1(float x) { return fminf(fmaxf(x, -1.0f), 1.0f); }
static __device__ __forceinline__ unsigned packbf(float a, float b) {
    __nv_bfloat162 t = __floats2bfloat162_rn(a, b);
    return *(unsigned*)&t;
}
static __device__ __forceinline__ int ld_acq(const int* p) {
    int v;
    asm volatile("ld.acquire.gpu.global.b32 %0,[%1];" : "=r"(v) : "l"(p) : "memory");
    return v;
}
static __device__ __forceinline__ void st_rel(int* p, int v) {
    asm volatile("st.release.gpu.global.b32 [%0],%1;" :: "l"(p), "r"(v) : "memory");
}
static __device__ __forceinline__ void cpa16(uint32_t dst, const void* src) {
    asm volatile("cp.async.cg.shared.global [%0],[%1],16;\n" :: "r"(dst), "l"(src));
}
#define CP_COMMIT() asm volatile("cp.async.commit_group;\n")
#define CP_WAIT(n)  asm volatile("cp.async.wait_group %0;\n" :: "n"(n))

#define LDSM4(R, addr) \
    asm volatile("ldmatrix.sync.aligned.m8n8.x4.shared.b16 {%0,%1,%2,%3},[%4];" \
        : "=r"((R)[0]), "=r"((R)[1]), "=r"((R)[2]), "=r"((R)[3]) : "r"(addr))
#define LDSM2T(R, addr) \
    asm volatile("ldmatrix.sync.aligned.m8n8.x2.trans.shared.b16 {%0,%1},[%2];" \
        : "=r"((R)[0]), "=r"((R)[1]) : "r"(addr))
#define MMA_BF16(C, A, B) \
    asm volatile("mma.sync.aligned.m16n8k16.row.col.f32.bf16.bf16.f32 " \
        "{%0,%1,%2,%3},{%4,%5,%6,%7},{%8,%9},{%0,%1,%2,%3};" \
        : "+f"((C)[0]), "+f"((C)[1]), "+f"((C)[2]), "+f"((C)[3]) \
        : "r"((A)[0]), "r"((A)[1]), "r"((A)[2]), "r"((A)[3]), "r"((B)[0]), "r"((B)[1]))

// ---------------- kernel: reset-dtype detection + flag reset ----------------
__global__ void k_detect(const unsigned char* __restrict__ r) {
    __shared__ int nz;
    if (threadIdx.x == 0) nz = 0;
    __syncthreads();
    for (int i = threadIdx.x; i < 128 * 32; i += blockDim.x) g_flag[i] = 0;
    int loc = 0;
    for (int i = threadIdx.x; i < TT * BB; i += blockDim.x)
        if ((i & 3) && r[i]) loc = 1;
    if (loc) atomicOr(&nz, 1);
    __syncthreads();
    if (threadIdx.x == 0) g_r_u8 = nz;
}

// ---------------- conversion kernels ----------------
__global__ void k_convert_x(const float* __restrict__ xs) {
    size_t i0 = ((size_t)blockIdx.x * blockDim.x + threadIdx.x) * 4;
    #pragma unroll
    for (int u = 0; u < 4; ++u) {
        size_t i = i0 + u;
        if (i < (size_t)MM * HH) {
            float v = xs[i];
            __nv_bfloat16 hi = __float2bfloat16(v);
            g_xhi[i] = hi;
            g_xlo[i] = __float2bfloat16(v - __bfloat162float(hi));
        }
    }
}
__global__ void k_convert_w(const float* __restrict__ Wi) {
    size_t i0 = ((size_t)blockIdx.x * blockDim.x + threadIdx.x) * 4;
    #pragma unroll
    for (int u = 0; u < 4; ++u) {
        size_t i = i0 + u;
        if (i < (size_t)HH * NN) {
            float v = Wi[i];
            __nv_bfloat16 hi = __float2bfloat16(v);
            g_whi[i] = hi;
            g_wlo[i] = __float2bfloat16(v - __bfloat162float(hi));
        }
    }
}

// ---------------- kernel: h init (bf16 hi/lo planes, [b][k]) ----------------
__global__ void k_hinit(const float* __restrict__ h0, const void* __restrict__ resets) {
    const int ru8 = g_r_u8;
    const unsigned char* r8 = (const unsigned char*)resets;
    const int* r32 = (const int*)resets;
    for (int idx = threadIdx.x + blockIdx.x * blockDim.x; idx < HH * BB;
         idx += blockDim.x * gridDim.x) {
        int b = idx >> 9, k = idx & 511;
        bool rs = ru8 ? (r8[b] != 0) : (r32[b] != 0);
        float hv = rs ? 0.0f : h0[b * HH + k];
        __nv_bfloat16 hi = __float2bfloat16(hv);
        g_hb[0][0][idx] = hi;
        g_hb[0][1][idx] = __float2bfloat16(hv - __bfloat162float(hi));
    }
}

// ---------------- kernel: zx = x @ Wi  (bf16 3-split tensor-core GEMM) ----------------
#define AROW 24
#define BROW 136

#define LOAD_STAGE(buf, ks) do {                                                           \
    const int kb_ = (ks) * 16;                                                             \
    _Pragma("unroll")                                                                      \
    for (int j_ = 0; j_ < 4; ++j_) {                                                       \
        int id_ = tid + 256 * j_;                                                          \
        if (id_ < 512) {                                                                   \
            int plane_ = id_ >> 8; int r_ = id_ & 255; int row_ = r_ >> 1; int half_ = r_ & 1; \
            const __nv_bfloat16* src_ = (plane_ ? g_xlo : g_xhi)                           \
                + (size_t)(mbase + row_) * HH + kb_ + half_ * 8;                           \
            uint32_t dst_ = Abase + (((buf) * 2 + plane_) * 128 * AROW + row_ * AROW + half_ * 8) * 2; \
            cpa16(dst_, src_);                                                             \
        } else {                                                                           \
            int id2_ = id_ - 512; int plane_ = id2_ >> 8; int r_ = id2_ & 255;             \
            int krow_ = r_ >> 4; int seg_ = r_ & 15;                                       \
            const __nv_bfloat16* src_ = (plane_ ? g_wlo : g_whi)                           \
                + (size_t)(kb_ + krow_) * NN + nbase + seg_ * 8;                           \
            uint32_t dst_ = Bbase + (((buf) * 2 + plane_) * 16 * BROW + krow_ * BROW + seg_ * 8) * 2; \
            cpa16(dst_, src_);                                                             \
        }                                                                                  \
    } } while (0)

__global__ __launch_bounds__(256) void k_mm_pre() {
    __shared__ __align__(128) __nv_bfloat16 Asm[2][2][128 * AROW];
    __shared__ __align__(128) __nv_bfloat16 Bsm[2][2][16 * BROW];
    const int tid = threadIdx.x;
    const int nbase = blockIdx.x * 128;
    const int mbase = blockIdx.y * 128;
    const int wid = tid >> 5, lane = tid & 31;
    const int wm = wid & 1, wn = wid >> 1;

    uint32_t Abase = (uint32_t)__cvta_generic_to_shared(&Asm[0][0][0]);
    uint32_t Bbase = (uint32_t)__cvta_generic_to_shared(&Bsm[0][0][0]);

    const int gid = lane >> 2, tig = lane & 3;
    const int arow = (lane & 7) + 8 * ((lane >> 3) & 1);
    const int acol = (lane >> 4) * 8;
    const int bk = lane & 15;

    float c[4][4][4] = {};

    LOAD_STAGE(0, 0);
    CP_COMMIT();

    #pragma unroll 1
    for (int ks = 0; ks < 32; ++ks) {
        const int buf = ks & 1;
        if (ks < 31) {
            LOAD_STAGE((ks + 1) & 1, ks + 1);
            CP_COMMIT();
            CP_WAIT(1);
        } else {
            CP_WAIT(0);
        }
        __syncthreads();

        uint32_t a_hi[4][4], a_lo[4][4];
        #pragma unroll
        for (int mi = 0; mi < 4; ++mi) {
            int rowoff = wm * 64 + mi * 16 + arow;
            uint32_t ah = Abase + ((buf * 2 + 0) * 128 * AROW + rowoff * AROW + acol) * 2;
            uint32_t al = Abase + ((buf * 2 + 1) * 128 * AROW + rowoff * AROW + acol) * 2;
            LDSM4(a_hi[mi], ah);
            LDSM4(a_lo[mi], al);
        }
        uint32_t bhf[4][2], blf[4][2];
        #pragma unroll
        for (int ni = 0; ni < 4; ++ni) {
            int n0 = wn * 32 + ni * 8;
            uint32_t bh = Bbase + ((buf * 2 + 0) * 16 * BROW + bk * BROW + n0) * 2;
            uint32_t bl = Bbase + ((buf * 2 + 1) * 16 * BROW + bk * BROW + n0) * 2;
            LDSM2T(bhf[ni], bh);
            LDSM2T(blf[ni], bl);
        }
        #pragma unroll
        for (int mi = 0; mi < 4; ++mi)
            #pragma unroll
            for (int ni = 0; ni < 4; ++ni) {
                MMA_BF16(c[mi][ni], a_hi[mi], bhf[ni]);
                MMA_BF16(c[mi][ni], a_hi[mi], blf[ni]);
                MMA_BF16(c[mi][ni], a_lo[mi], bhf[ni]);
            }
        __syncthreads();
    }

    #pragma unroll
    for (int mi = 0; mi < 4; ++mi)
        #pragma unroll
        for (int ni = 0; ni < 4; ++ni) {
            int m0 = mbase + wm * 64 + mi * 16 + gid;
            int n = nbase + wn * 32 + ni * 8 + tig * 2;
            *(float2*)(g_zx + (size_t)m0 * NN + n) = make_float2(c[mi][ni][0], c[mi][ni][1]);
            *(float2*)(g_zx + (size_t)(m0 + 8) * NN + n) = make_float2(c[mi][ni][2], c[mi][ni][3]);
        }
}

// ---------------- kernel: persistent scanned-LSTM (tensor-core h @ Wh) ----------------
// 128 CTAs x 256 threads. CTA owns 16 z-cols: col(l) = (l>>2)*512 + cta*4 + (l&3).
// Warps K-split: warp w owns k in [64w, 64w+64) -> depends only on CTAs 16w..16w+16.
// Per step, each warp stages its own h k-slice (both planes) into SMEM via cp.async
// (full-sector 16B chunks), then feeds fragments with ldmatrix. 2-half pipeline.
#define HROW 520                         // bf16 per SMEM h row (1040 B; rows shift 4 banks)
#define HPLANE (64 * HROW)               // one plane
#define HSM_BYTES (2 * HPLANE * 2)       // 133120
#define ZP 18
#define SMEM_TOTAL (HSM_BYTES + 8 * 64 * ZP * 4)   // 169984

__global__ __launch_bounds__(256, 1)
void lstm_main(const float* __restrict__ Wh, const float* __restrict__ bias,
               const float* __restrict__ c0, const void* __restrict__ resets,
               float* __restrict__ ys) {
    extern __shared__ __align__(128) char smem[];
    __nv_bfloat16* hsm = (__nv_bfloat16*)smem;          // [2 planes][64][HROW]
    float* zsb = (float*)(smem + HSM_BYTES);            // [8][64][ZP]
    const uint32_t hb32 = (uint32_t)__cvta_generic_to_shared(hsm);

    const int tid = threadIdx.x;
    const int cta = blockIdx.x;
    const int wid = tid >> 5, lane = tid & 31;
    const int gid = lane >> 2, tig = lane & 3;
    const int wk = wid * 64;

    const int lane7 = lane & 7, lane3 = lane >> 3;       // stage identity
    const int arow = (lane & 7) + 8 * ((lane >> 3) & 1); // ldmatrix identity
    const int acol = (lane >> 4) * 8;

    // this warp's producer flag (one of the 16 CTAs owning our k-slice)
    const int* myflag = g_flag + ((wid * 16 + (lane & 15)) << 5);

    // ---- build register-resident B fragments from fp32 Wh (once) ----
    unsigned bh[2][4][2], bl[2][4][2];
    #pragma unroll
    for (int nt = 0; nt < 2; ++nt) {
        const int l = nt * 8 + gid;
        const int gcol = (l >> 2) * 512 + cta * 4 + (l & 3);
        #pragma unroll
        for (int kt = 0; kt < 4; ++kt) {
            const int k0 = wk + kt * 16 + 2 * tig;
            float f0 = Wh[(size_t)k0 * NN + gcol];
            float f1 = Wh[(size_t)(k0 + 1) * NN + gcol];
            float f2 = Wh[(size_t)(k0 + 8) * NN + gcol];
            float f3 = Wh[(size_t)(k0 + 9) * NN + gcol];
            float h0f = __bfloat162float(__float2bfloat16(f0));
            float h1f = __bfloat162float(__float2bfloat16(f1));
            float h2f = __bfloat162float(__float2bfloat16(f2));
            float h3f = __bfloat162float(__float2bfloat16(f3));
            bh[nt][kt][0] = packbf(h0f, h1f);
            bh[nt][kt][1] = packbf(h2f, h3f);
            bl[nt][kt][0] = packbf(f0 - h0f, f1 - h1f);
            bl[nt][kt][1] = packbf(f2 - h2f, f3 - h3f);
        }
    }

    // ---- epilogue identity: one (b, j) element ----
    const int eb = tid >> 2;
    const int ej = tid & 3;
    const int jcol = cta * 4 + ej;
    float c = c0[eb * HH + jcol];
    const float bi = bias[jcol];
    const float bf = bias[512 + jcol];
    const float bg = bias[1024 + jcol];
    const float bo = bias[1536 + jcol];
    const int ru8 = g_r_u8;
    const unsigned char* r8 = (const unsigned char*)resets;
    const int* r32 = (const int*)resets;

    int* ctaflag = g_flag + (cta << 5);

    for (int t = 0; t < TT; ++t) {
        // zx prefetch (DRAM) — issue BEFORE the flag wait so latency hides under it
        const float* zxr = g_zx + (size_t)(t * BB + eb) * NN + jcol;
        float z0 = __ldcg(zxr);
        float z1 = __ldcg(zxr + 512);
        float z2 = __ldcg(zxr + 1024);
        float z3 = __ldcg(zxr + 1536);

        // ---- dependency wait: this warp's 16 producers published h[t] ----
        if (t > 0) {
            int v = ld_acq(myflag);
            unsigned ok = __ballot_sync(0xffffffffu, v >= t);
            while (ok != 0xffffffffu) {
                __nanosleep(32);
                v = ld_acq(myflag);
                ok = __ballot_sync(0xffffffffu, v >= t);
            }
        }

        const __nv_bfloat16* hhi = g_hb[t & 1][0];
        const __nv_bfloat16* hlo = g_hb[t & 1][1];

        // ---- stage this warp's k-slice into SMEM (2 halves, pipelined) ----
        #pragma unroll
        for (int hh = 0; hh < 2; ++hh) {
            const int seg = hh * 4 + lane3;
            const int k0 = wk + seg * 8;
            #pragma unroll
            for (int i = 0; i < 8; ++i) {
                const int b = i * 8 + lane7;
                cpa16(hb32 + (b * HROW + k0) * 2, hhi + b * 512 + k0);
                cpa16(hb32 + (HPLANE + b * HROW + k0) * 2, hlo + b * 512 + k0);
            }
            CP_COMMIT();
        }

        float acc[4][2][4];
        #pragma unroll
        for (int mt = 0; mt < 4; ++mt)
            #pragma unroll
            for (int nt = 0; nt < 2; ++nt)
                #pragma unroll
                for (int q = 0; q < 4; ++q) acc[mt][nt][q] = 0.0f;

        CP_WAIT(1);   // half 0 (kt 0,1) resident
        #pragma unroll
        for (int kt = 0; kt < 4; ++kt) {
            if (kt == 2) CP_WAIT(0);   // half 1 (kt 2,3) resident
            unsigned ahi[4][4], alo[4][4];
            #pragma unroll
            for (int mt = 0; mt < 4; ++mt) {
                const int r0 = mt * 16 + arow;
                const uint32_t col = (uint32_t)(wk + kt * 16 + acol);
                uint32_t ah = hb32 + (r0 * HROW + col) * 2;
                uint32_t al = ah + HPLANE * 2;
                LDSM4(ahi[mt], ah);
                LDSM4(alo[mt], al);
            }
            #pragma unroll
            for (int mt = 0; mt < 4; ++mt)
                #pragma unroll
                for (int nt = 0; nt < 2; ++nt) {
                    MMA_BF16(acc[mt][nt], ahi[mt], bh[nt][kt]);
                    MMA_BF16(acc[mt][nt], ahi[mt], bl[nt][kt]);
                    MMA_BF16(acc[mt][nt], alo[mt], bh[nt][kt]);
                }
        }

        // write K-split partials
        #pragma unroll
        for (int mt = 0; mt < 4; ++mt)
            #pragma unroll
            for (int nt = 0; nt < 2; ++nt) {
                const int r0 = mt * 16 + gid;
                const int col = nt * 8 + 2 * tig;
                *(float2*)&zsb[(wid * 64 + r0) * ZP + col] =
                    make_float2(acc[mt][nt][0], acc[mt][nt][1]);
                *(float2*)&zsb[(wid * 64 + r0 + 8) * ZP + col] =
                    make_float2(acc[mt][nt][2], acc[mt][nt][3]);
            }
        __syncthreads();

        // ---- epilogue ----
        {
            float zi = z0 + bi, zf = z1 + bf, zg = z2 + bg, zo = z3 + bo;
            #pragma unroll
            for (int s = 0; s < 8; ++s) {
                const float* zr = zsb + (s * 64 + eb) * ZP;
                zi += zr[ej];
                zf += zr[4 + ej];
                zg += zr[8 + ej];
                zo += zr[12 + ej];
            }

            bool rs = ru8 ? (r8[t * BB + eb] != 0) : (r32[t * BB + eb] != 0);
            if (rs) c = 0.0f;

            float iv = sigf(zi);
            float fv = sigf(zf);
            float gv = tanhf(zg);
            float ov = sigf(zo);
            float ncr = fv * c + iv * gv;
            float nh = ov * tanhf(ncr);
            c = clampf1(ncr);
            float nhc = clampf1(nh);

            ys[(size_t)t * BB * HH + (size_t)eb * HH + jcol] = nhc;
            if (t + 1 < TT) {
                bool rs2 = ru8 ? (r8[(t + 1) * BB + eb] != 0) : (r32[(t + 1) * BB + eb] != 0);
                float hv = rs2 ? 0.0f : nhc;
                __nv_bfloat16 hi = __float2bfloat16(hv);
                const int nb = (t + 1) & 1;
                g_hb[nb][0][eb * HH + jcol] = hi;
                g_hb[nb][1][eb * HH + jcol] = __float2bfloat16(hv - __bfloat162float(hi));
            }
        }

        // ---- publish: all our h stores done -> release our epoch flag ----
        __syncthreads();
        if (tid == 0) {
            __threadfence();
            st_rel(ctaflag, t + 1);
        }
    }
}

// ---------------- launch ----------------
extern "C" void kernel_launch(void* const* d_in, const int* in_sizes, int n_in,
                              void* d_out, int out_size) {
    const float* xs     = (const float*)d_in[0];
    const void*  resets = d_in[1];
    const float* c0     = (const float*)d_in[2];
    const float* h0     = (const float*)d_in[3];
    const float* Wi     = (const float*)d_in[4];
    const float* Wh     = (const float*)d_in[5];
    const float* bias   = (const float*)d_in[6];
    float* ys = (float*)d_out;

    cudaFuncSetAttribute(lstm_main, cudaFuncAttributeMaxDynamicSharedMemorySize, SMEM_TOTAL);

    k_detect<<<1, 256>>>((const unsigned char*)resets);
    k_convert_x<<<16384, 256>>>(xs);
    k_convert_w<<<1024, 256>>>(Wi);
    k_hinit<<<32, 256>>>(h0, resets);
    dim3 gpre(16, 256);
    k_mm_pre<<<gpre, 256>>>();
    lstm_main<<<128, 256, SMEM_TOTAL>>>(Wh, bias, c0, resets, ys);
}

// round 15
// speedup vs baseline: 1.7996x; 1.3814x over previous
#include <cuda_runtime.h>
#include <cuda_bf16.h>
#include <cstdint>

#define TT 512
#define BB 64
#define HH 512
#define MM (TT * BB)        // 32768
#define NN (4 * HH)         // 2048
#define GB 16               // batch rows per group
#define GCTAS 32            // CTAs per group

// ---------------- device scratch (static) ----------------
__device__ float g_zx[(size_t)MM * NN];                       // 256 MB, [m][n]
__device__ __nv_bfloat16 g_xhi[(size_t)MM * HH];              // 32 MB
__device__ __nv_bfloat16 g_xlo[(size_t)MM * HH];              // 32 MB
__device__ __nv_bfloat16 g_whi[(size_t)HH * NN];              // 2 MB
__device__ __nv_bfloat16 g_wlo[(size_t)HH * NN];              // 2 MB
__device__ __align__(128) __nv_bfloat16 g_hb[2][2][BB * HH];  // h bf16 planes [buf][hi/lo][b][k]
__device__ int g_flag[128 * 32];                              // per-CTA epoch flags, 128B stride
__device__ int g_r_u8;

// ---------------- helpers ----------------
static __device__ __forceinline__ float sigf(float x) { return 1.0f / (1.0f + __expf(-x)); }
static __device__ __forceinline__ float clampf1(float x) { return fminf(fmaxf(x, -1.0f), 1.0f); }
static __device__ __forceinline__ unsigned packbf(float a, float b) {
    __nv_bfloat162 t = __floats2bfloat162_rn(a, b);
    return *(unsigned*)&t;
}
static __device__ __forceinline__ int ld_acq(const int* p) {
    int v;
    asm volatile("ld.acquire.gpu.global.b32 %0,[%1];" : "=r"(v) : "l"(p) : "memory");
    return v;
}
static __device__ __forceinline__ void st_rel(int* p, int v) {
    asm volatile("st.release.gpu.global.b32 [%0],%1;" :: "l"(p), "r"(v) : "memory");
}
static __device__ __forceinline__ void cpa16(uint32_t dst, const void* src) {
    asm volatile("cp.async.cg.shared.global [%0],[%1],16;\n" :: "r"(dst), "l"(src));
}
#define CP_COMMIT() asm volatile("cp.async.commit_group;\n")
#define CP_WAIT(n)  asm volatile("cp.async.wait_group %0;\n" :: "n"(n))

#define LDSM4(R, addr) \
    asm volatile("ldmatrix.sync.aligned.m8n8.x4.shared.b16 {%0,%1,%2,%3},[%4];" \
        : "=r"((R)[0]), "=r"((R)[1]), "=r"((R)[2]), "=r"((R)[3]) : "r"(addr))
#define LDSM2T(R, addr) \
    asm volatile("ldmatrix.sync.aligned.m8n8.x2.trans.shared.b16 {%0,%1},[%2];" \
        : "=r"((R)[0]), "=r"((R)[1]) : "r"(addr))
#define MMA_BF16(C, A, B) \
    asm volatile("mma.sync.aligned.m16n8k16.row.col.f32.bf16.bf16.f32 " \
        "{%0,%1,%2,%3},{%4,%5,%6,%7},{%8,%9},{%0,%1,%2,%3};" \
        : "+f"((C)[0]), "+f"((C)[1]), "+f"((C)[2]), "+f"((C)[3]) \
        : "r"((A)[0]), "r"((A)[1]), "r"((A)[2]), "r"((A)[3]), "r"((B)[0]), "r"((B)[1]))

// ---------------- kernel: reset-dtype detection + flag reset ----------------
__global__ void k_detect(const unsigned char* __restrict__ r) {
    __shared__ int nz;
    if (threadIdx.x == 0) nz = 0;
    __syncthreads();
    for (int i = threadIdx.x; i < 128 * 32; i += blockDim.x) g_flag[i] = 0;
    int loc = 0;
    for (int i = threadIdx.x; i < TT * BB; i += blockDim.x)
        if ((i & 3) && r[i]) loc = 1;
    if (loc) atomicOr(&nz, 1);
    __syncthreads();
    if (threadIdx.x == 0) g_r_u8 = nz;
}

// ---------------- conversion kernels ----------------
__global__ void k_convert_x(const float* __restrict__ xs) {
    size_t i0 = ((size_t)blockIdx.x * blockDim.x + threadIdx.x) * 4;
    #pragma unroll
    for (int u = 0; u < 4; ++u) {
        size_t i = i0 + u;
        if (i < (size_t)MM * HH) {
            float v = xs[i];
            __nv_bfloat16 hi = __float2bfloat16(v);
            g_xhi[i] = hi;
            g_xlo[i] = __float2bfloat16(v - __bfloat162float(hi));
        }
    }
}
__global__ void k_convert_w(const float* __restrict__ Wi) {
    size_t i0 = ((size_t)blockIdx.x * blockDim.x + threadIdx.x) * 4;
    #pragma unroll
    for (int u = 0; u < 4; ++u) {
        size_t i = i0 + u;
        if (i < (size_t)HH * NN) {
            float v = Wi[i];
            __nv_bfloat16 hi = __float2bfloat16(v);
            g_whi[i] = hi;
            g_wlo[i] = __float2bfloat16(v - __bfloat162float(hi));
        }
    }
}

// ---------------- kernel: h init (bf16 hi/lo planes, [b][k]) ----------------
__global__ void k_hinit(const float* __restrict__ h0, const void* __restrict__ resets) {
    const int ru8 = g_r_u8;
    const unsigned char* r8 = (const unsigned char*)resets;
    const int* r32 = (const int*)resets;
    for (int idx = threadIdx.x + blockIdx.x * blockDim.x; idx < HH * BB;
         idx += blockDim.x * gridDim.x) {
        int b = idx >> 9, k = idx & 511;
        bool rs = ru8 ? (r8[b] != 0) : (r32[b] != 0);
        float hv = rs ? 0.0f : h0[b * HH + k];
        __nv_bfloat16 hi = __float2bfloat16(hv);
        g_hb[0][0][idx] = hi;
        g_hb[0][1][idx] = __float2bfloat16(hv - __bfloat162float(hi));
    }
}

// ---------------- kernel: zx = x @ Wi  (bf16 3-split tensor-core GEMM) ----------------
#define AROW 24
#define BROW 136

#define LOAD_STAGE(buf, ks) do {                                                           \
    const int kb_ = (ks) * 16;                                                             \
    _Pragma("unroll")                                                                      \
    for (int j_ = 0; j_ < 4; ++j_) {                                                       \
        int id_ = tid + 256 * j_;                                                          \
        if (id_ < 512) {                                                                   \
            int plane_ = id_ >> 8; int r_ = id_ & 255; int row_ = r_ >> 1; int half_ = r_ & 1; \
            const __nv_bfloat16* src_ = (plane_ ? g_xlo : g_xhi)                           \
                + (size_t)(mbase + row_) * HH + kb_ + half_ * 8;                           \
            uint32_t dst_ = Abase + (((buf) * 2 + plane_) * 128 * AROW + row_ * AROW + half_ * 8) * 2; \
            cpa16(dst_, src_);                                                             \
        } else {                                                                           \
            int id2_ = id_ - 512; int plane_ = id2_ >> 8; int r_ = id2_ & 255;             \
            int krow_ = r_ >> 4; int seg_ = r_ & 15;                                       \
            const __nv_bfloat16* src_ = (plane_ ? g_wlo : g_whi)                           \
                + (size_t)(kb_ + krow_) * NN + nbase + seg_ * 8;                           \
            uint32_t dst_ = Bbase + (((buf) * 2 + plane_) * 16 * BROW + krow_ * BROW + seg_ * 8) * 2; \
            cpa16(dst_, src_);                                                             \
        }                                                                                  \
    } } while (0)

__global__ __launch_bounds__(256) void k_mm_pre() {
    __shared__ __align__(128) __nv_bfloat16 Asm[2][2][128 * AROW];
    __shared__ __align__(128) __nv_bfloat16 Bsm[2][2][16 * BROW];
    const int tid = threadIdx.x;
    const int nbase = blockIdx.x * 128;
    const int mbase = blockIdx.y * 128;
    const int wid = tid >> 5, lane = tid & 31;
    const int wm = wid & 1, wn = wid >> 1;

    uint32_t Abase = (uint32_t)__cvta_generic_to_shared(&Asm[0][0][0]);
    uint32_t Bbase = (uint32_t)__cvta_generic_to_shared(&Bsm[0][0][0]);

    const int gid = lane >> 2, tig = lane & 3;
    const int arow = (lane & 7) + 8 * ((lane >> 3) & 1);
    const int acol = (lane >> 4) * 8;
    const int bk = lane & 15;

    float c[4][4][4] = {};

    LOAD_STAGE(0, 0);
    CP_COMMIT();

    #pragma unroll 1
    for (int ks = 0; ks < 32; ++ks) {
        const int buf = ks & 1;
        if (ks < 31) {
            LOAD_STAGE((ks + 1) & 1, ks + 1);
            CP_COMMIT();
            CP_WAIT(1);
        } else {
            CP_WAIT(0);
        }
        __syncthreads();

        uint32_t a_hi[4][4], a_lo[4][4];
        #pragma unroll
        for (int mi = 0; mi < 4; ++mi) {
            int rowoff = wm * 64 + mi * 16 + arow;
            uint32_t ah = Abase + ((buf * 2 + 0) * 128 * AROW + rowoff * AROW + acol) * 2;
            uint32_t al = Abase + ((buf * 2 + 1) * 128 * AROW + rowoff * AROW + acol) * 2;
            LDSM4(a_hi[mi], ah);
            LDSM4(a_lo[mi], al);
        }
        uint32_t bhf[4][2], blf[4][2];
        #pragma unroll
        for (int ni = 0; ni < 4; ++ni) {
            int n0 = wn * 32 + ni * 8;
            uint32_t bh = Bbase + ((buf * 2 + 0) * 16 * BROW + bk * BROW + n0) * 2;
            uint32_t bl = Bbase + ((buf * 2 + 1) * 16 * BROW + bk * BROW + n0) * 2;
            LDSM2T(bhf[ni], bh);
            LDSM2T(blf[ni], bl);
        }
        #pragma unroll
        for (int mi = 0; mi < 4; ++mi)
            #pragma unroll
            for (int ni = 0; ni < 4; ++ni) {
                MMA_BF16(c[mi][ni], a_hi[mi], bhf[ni]);
                MMA_BF16(c[mi][ni], a_hi[mi], blf[ni]);
                MMA_BF16(c[mi][ni], a_lo[mi], bhf[ni]);
            }
        __syncthreads();
    }

    #pragma unroll
    for (int mi = 0; mi < 4; ++mi)
        #pragma unroll
        for (int ni = 0; ni < 4; ++ni) {
            int m0 = mbase + wm * 64 + mi * 16 + gid;
            int n = nbase + wn * 32 + ni * 8 + tig * 2;
            *(float2*)(g_zx + (size_t)m0 * NN + n) = make_float2(c[mi][ni][0], c[mi][ni][1]);
            *(float2*)(g_zx + (size_t)(m0 + 8) * NN + n) = make_float2(c[mi][ni][2], c[mi][ni][3]);
        }
}

// ---------------- kernel: persistent scanned-LSTM, 4 independent batch groups ----------------
// Group g = cta>>5 owns batch rows [16g, 16g+16). CTA lc = cta&31 owns state cols
// [16lc, 16lc+16) -> 64 z-cols {gate*512 + 16lc + jj}. Warps K-split 8x64.
// Warp ks's producers: CTAs (group, 4ks..4ks+4). No cross-group sync at all.
#define HROW 520                          // bf16 per SMEM h row (1040 B)
#define HPLANE (GB * HROW)                // one plane (16 rows)
#define HSM_BYTES (2 * HPLANE * 2)        // 33280
#define ZSP 80                            // floats per zs row (conflict-free)
#define SMEM_TOTAL (HSM_BYTES + 8 * GB * ZSP * 4)   // 33280 + 40960 = 74240

__global__ __launch_bounds__(256, 1)
void lstm_main(const float* __restrict__ Wh, const float* __restrict__ bias,
               const float* __restrict__ c0, const void* __restrict__ resets,
               float* __restrict__ ys) {
    extern __shared__ __align__(128) char smem[];
    __nv_bfloat16* hsm = (__nv_bfloat16*)smem;          // [2 planes][16][HROW]
    float* zsb = (float*)(smem + HSM_BYTES);            // [8][16][ZSP]
    const uint32_t hb32 = (uint32_t)__cvta_generic_to_shared(hsm);

    const int tid = threadIdx.x;
    const int cta = blockIdx.x;
    const int grp = cta >> 5;          // 0..3
    const int lc  = cta & 31;          // 0..31
    const int wid = tid >> 5, lane = tid & 31;
    const int gid = lane >> 2, tig = lane & 3;
    const int wk = wid * 64;

    const int srow = lane & 15, schunk = lane >> 4;      // stage identity
    const int arow = (lane & 7) + 8 * ((lane >> 3) & 1); // ldmatrix row (== lane&15 for <16)
    const int acol = (lane >> 4) * 8;

    // warp's 4 producer flags (CTAs grp*32 + 4*wid .. +4), lanes 0..3 poll
    const int* myflag = g_flag + ((grp * GCTAS + wid * 4 + (lane & 3)) << 5);

    // ---- build register-resident B fragments from fp32 Wh (once) ----
    unsigned bh[8][4][2], bl[8][4][2];
    #pragma unroll
    for (int nt = 0; nt < 8; ++nt) {
        const int n = nt * 8 + gid;                       // 0..63
        const int gcol = (n >> 4) * 512 + lc * 16 + (n & 15);
        #pragma unroll
        for (int kt = 0; kt < 4; ++kt) {
            const int k0 = wk + kt * 16 + 2 * tig;
            float f0 = Wh[(size_t)k0 * NN + gcol];
            float f1 = Wh[(size_t)(k0 + 1) * NN + gcol];
            float f2 = Wh[(size_t)(k0 + 8) * NN + gcol];
            float f3 = Wh[(size_t)(k0 + 9) * NN + gcol];
            float h0f = __bfloat162float(__float2bfloat16(f0));
            float h1f = __bfloat162float(__float2bfloat16(f1));
            float h2f = __bfloat162float(__float2bfloat16(f2));
            float h3f = __bfloat162float(__float2bfloat16(f3));
            bh[nt][kt][0] = packbf(h0f, h1f);
            bh[nt][kt][1] = packbf(h2f, h3f);
            bl[nt][kt][0] = packbf(f0 - h0f, f1 - h1f);
            bl[nt][kt][1] = packbf(f2 - h2f, f3 - h3f);
        }
    }

    // ---- epilogue identity: one (local b, local j) element ----
    const int eb = tid >> 4;           // 0..15 local batch row
    const int ej = tid & 15;           // 0..15 local state col
    const int gb = grp * GB + eb;      // global batch row
    const int jcol = lc * 16 + ej;     // global state col
    float c = c0[gb * HH + jcol];
    const float bi = bias[jcol];
    const float bf = bias[512 + jcol];
    const float bg = bias[1024 + jcol];
    const float bo = bias[1536 + jcol];
    const int ru8 = g_r_u8;
    const unsigned char* r8 = (const unsigned char*)resets;
    const int* r32 = (const int*)resets;

    int* ctaflag = g_flag + (cta << 5);

    for (int t = 0; t < TT; ++t) {
        // zx prefetch (DRAM) — issued before the flag wait to hide latency
        const float* zxr = g_zx + (size_t)(t * BB + gb) * NN + jcol;
        float z0 = __ldcg(zxr);
        float z1 = __ldcg(zxr + 512);
        float z2 = __ldcg(zxr + 1024);
        float z3 = __ldcg(zxr + 1536);

        // ---- dependency wait: 4 producers in our group published h[t] ----
        if (t > 0) {
            int v = (lane < 4) ? ld_acq(myflag) : t;
            unsigned ok = __ballot_sync(0xffffffffu, v >= t);
            while (ok != 0xffffffffu) {
                __nanosleep(32);
                v = (lane < 4) ? ld_acq(myflag) : t;
                ok = __ballot_sync(0xffffffffu, v >= t);
            }
        }

        const __nv_bfloat16* hhi = g_hb[t & 1][0] + (size_t)grp * GB * HH;
        const __nv_bfloat16* hlo = g_hb[t & 1][1] + (size_t)grp * GB * HH;

        // ---- stage this warp's k-slice (16 rows x 64 k, 2 planes), 2 pipelined halves ----
        #pragma unroll
        for (int hh = 0; hh < 2; ++hh) {
            #pragma unroll
            for (int i = 0; i < 2; ++i) {
                const int k0 = wk + (hh * 4 + schunk + 2 * i) * 8;
                cpa16(hb32 + (srow * HROW + k0) * 2, hhi + srow * HH + k0);
                cpa16(hb32 + (HPLANE + srow * HROW + k0) * 2, hlo + srow * HH + k0);
            }
            CP_COMMIT();
        }

        float acc[8][4];
        #pragma unroll
        for (int nt = 0; nt < 8; ++nt)
            #pragma unroll
            for (int q = 0; q < 4; ++q) acc[nt][q] = 0.0f;

        CP_WAIT(1);   // half 0 (kt 0,1) resident
        #pragma unroll
        for (int kt = 0; kt < 4; ++kt) {
            if (kt == 2) CP_WAIT(0);   // half 1 resident
            unsigned ahi[4], alo[4];
            {
                const uint32_t col = (uint32_t)(wk + kt * 16 + acol);
                uint32_t ah = hb32 + (arow * HROW + col) * 2;
                uint32_t al = ah + HPLANE * 2;
                LDSM4(ahi, ah);
                LDSM4(alo, al);
            }
            #pragma unroll
            for (int nt = 0; nt < 8; ++nt) {
                MMA_BF16(acc[nt], ahi, bh[nt][kt]);
                MMA_BF16(acc[nt], ahi, bl[nt][kt]);
                MMA_BF16(acc[nt], alo, bh[nt][kt]);
            }
        }

        // write K-split partials: zs[wid][row][ncol]
        #pragma unroll
        for (int nt = 0; nt < 8; ++nt) {
            const int col = nt * 8 + 2 * tig;
            *(float2*)&zsb[(wid * GB + gid) * ZSP + col] = make_float2(acc[nt][0], acc[nt][1]);
            *(float2*)&zsb[(wid * GB + gid + 8) * ZSP + col] = make_float2(acc[nt][2], acc[nt][3]);
        }
        __syncthreads();

        // ---- epilogue ----
        {
            float zi = z0 + bi, zf = z1 + bf, zg = z2 + bg, zo = z3 + bo;
            #pragma unroll
            for (int s = 0; s < 8; ++s) {
                const float* zr = zsb + (s * GB + eb) * ZSP;
                zi += zr[ej];
                zf += zr[16 + ej];
                zg += zr[32 + ej];
                zo += zr[48 + ej];
            }

            bool rs = ru8 ? (r8[t * BB + gb] != 0) : (r32[t * BB + gb] != 0);
            if (rs) c = 0.0f;

            float iv = sigf(zi);
            float fv = sigf(zf);
            float gv = tanhf(zg);
            float ov = sigf(zo);
            float ncr = fv * c + iv * gv;
            float nh = ov * tanhf(ncr);
            c = clampf1(ncr);
            float nhc = clampf1(nh);

            ys[(size_t)t * BB * HH + (size_t)gb * HH + jcol] = nhc;
            if (t + 1 < TT) {
                bool rs2 = ru8 ? (r8[(t + 1) * BB + gb] != 0) : (r32[(t + 1) * BB + gb] != 0);
                float hv = rs2 ? 0.0f : nhc;
                __nv_bfloat16 hi = __float2bfloat16(hv);
                const int nb = (t + 1) & 1;
                g_hb[nb][0][gb * HH + jcol] = hi;
                g_hb[nb][1][gb * HH + jcol] = __float2bfloat16(hv - __bfloat162float(hi));
            }
        }

        // ---- publish ----
        __syncthreads();
        if (tid == 0) {
            __threadfence();
            st_rel(ctaflag, t + 1);
        }
    }
}

// ---------------- launch ----------------
extern "C" void kernel_launch(void* const* d_in, const int* in_sizes, int n_in,
                              void* d_out, int out_size) {
    const float* xs     = (const float*)d_in[0];
    const void*  resets = d_in[1];
    const float* c0     = (const float*)d_in[2];
    const float* h0     = (const float*)d_in[3];
    const float* Wi     = (const float*)d_in[4];
    const float* Wh     = (const float*)d_in[5];
    const float* bias   = (const float*)d_in[6];
    float* ys = (float*)d_out;

    cudaFuncSetAttribute(lstm_main, cudaFuncAttributeMaxDynamicSharedMemorySize, SMEM_TOTAL);

    k_detect<<<1, 256>>>((const unsigned char*)resets);
    k_convert_x<<<16384, 256>>>(xs);
    k_convert_w<<<1024, 256>>>(Wi);
    k_hinit<<<32, 256>>>(h0, resets);
    dim3 gpre(16, 256);
    k_mm_pre<<<gpre, 256>>>();
    lstm_main<<<128, 256, SMEM_TOTAL>>>(Wh, bias, c0, resets, ys);
}

// round 16
// speedup vs baseline: 1.8378x; 1.0212x over previous
#include <cuda_runtime.h>
#include <cuda_bf16.h>
#include <cstdint>

#define TT 512
#define BB 64
#define HH 512
#define MM (TT * BB)        // 32768
#define NN (4 * HH)         // 2048
#define GB 16               // batch rows per group
#define GCTAS 32            // CTAs per group

// ---------------- device scratch (static) ----------------
__device__ float g_zx[(size_t)MM * NN];                       // 256 MB, [m][n]
__device__ __nv_bfloat16 g_xhi[(size_t)MM * HH];              // 32 MB
__device__ __nv_bfloat16 g_xlo[(size_t)MM * HH];              // 32 MB
__device__ __nv_bfloat16 g_whi[(size_t)HH * NN];              // 2 MB
__device__ __nv_bfloat16 g_wlo[(size_t)HH * NN];              // 2 MB
__device__ __align__(128) __nv_bfloat16 g_hb[2][2][BB * HH];  // h bf16 planes [buf][hi/lo][b][k]
__device__ int g_flag[1024 * 32];                             // per-WARP epoch flags, 128B stride
__device__ int g_r_u8;

// ---------------- helpers ----------------
static __device__ __forceinline__ float sigf(float x) { return 1.0f / (1.0f + __expf(-x)); }
static __device__ __forceinline__ float clampf1(float x) { return fminf(fmaxf(x, -1.0f), 1.0f); }
static __device__ __forceinline__ unsigned packbf(float a, float b) {
    __nv_bfloat162 t = __floats2bfloat162_rn(a, b);
    return *(unsigned*)&t;
}
static __device__ __forceinline__ int ld_acq(const int* p) {
    int v;
    asm volatile("ld.acquire.gpu.global.b32 %0,[%1];" : "=r"(v) : "l"(p) : "memory");
    return v;
}
static __device__ __forceinline__ void st_rel(int* p, int v) {
    asm volatile("st.release.gpu.global.b32 [%0],%1;" :: "l"(p), "r"(v) : "memory");
}
static __device__ __forceinline__ void cpa16(uint32_t dst, const void* src) {
    asm volatile("cp.async.cg.shared.global [%0],[%1],16;\n" :: "r"(dst), "l"(src));
}
#define CP_COMMIT() asm volatile("cp.async.commit_group;\n")
#define CP_WAIT(n)  asm volatile("cp.async.wait_group %0;\n" :: "n"(n))

#define LDSM4(R, addr) \
    asm volatile("ldmatrix.sync.aligned.m8n8.x4.shared.b16 {%0,%1,%2,%3},[%4];" \
        : "=r"((R)[0]), "=r"((R)[1]), "=r"((R)[2]), "=r"((R)[3]) : "r"(addr))
#define LDSM2T(R, addr) \
    asm volatile("ldmatrix.sync.aligned.m8n8.x2.trans.shared.b16 {%0,%1},[%2];" \
        : "=r"((R)[0]), "=r"((R)[1]) : "r"(addr))
#define MMA_BF16(C, A, B) \
    asm volatile("mma.sync.aligned.m16n8k16.row.col.f32.bf16.bf16.f32 " \
        "{%0,%1,%2,%3},{%4,%5,%6,%7},{%8,%9},{%0,%1,%2,%3};" \
        : "+f"((C)[0]), "+f"((C)[1]), "+f"((C)[2]), "+f"((C)[3]) \
        : "r"((A)[0]), "r"((A)[1]), "r"((A)[2]), "r"((A)[3]), "r"((B)[0]), "r"((B)[1]))

// ---------------- kernel 1: reset-dtype detection + flag reset ----------------
__global__ void k_detect(const unsigned char* __restrict__ r) {
    __shared__ int nz;
    if (threadIdx.x == 0) nz = 0;
    __syncthreads();
    for (int i = threadIdx.x; i < 1024 * 32; i += blockDim.x) g_flag[i] = 0;
    int loc = 0;
    for (int i = threadIdx.x; i < TT * BB; i += blockDim.x)
        if ((i & 3) && r[i]) loc = 1;
    if (loc) atomicOr(&nz, 1);
    __syncthreads();
    if (threadIdx.x == 0) g_r_u8 = nz;
}

// ---------------- kernel 2: fused prep (convert x, convert Wi, init h) ----------------
// blocks [0,16384): x hi/lo split; [16384,17408): Wi hi/lo split; [17408,17440): h init.
__global__ void k_prep(const float* __restrict__ xs, const float* __restrict__ Wi,
                       const float* __restrict__ h0, const void* __restrict__ resets) {
    const int bid = blockIdx.x;
    if (bid < 16384) {
        size_t i0 = ((size_t)bid * blockDim.x + threadIdx.x) * 4;
        #pragma unroll
        for (int u = 0; u < 4; ++u) {
            size_t i = i0 + u;
            if (i < (size_t)MM * HH) {
                float v = xs[i];
                __nv_bfloat16 hi = __float2bfloat16(v);
                g_xhi[i] = hi;
                g_xlo[i] = __float2bfloat16(v - __bfloat162float(hi));
            }
        }
    } else if (bid < 17408) {
        size_t i0 = ((size_t)(bid - 16384) * blockDim.x + threadIdx.x) * 4;
        #pragma unroll
        for (int u = 0; u < 4; ++u) {
            size_t i = i0 + u;
            if (i < (size_t)HH * NN) {
                float v = Wi[i];
                __nv_bfloat16 hi = __float2bfloat16(v);
                g_whi[i] = hi;
                g_wlo[i] = __float2bfloat16(v - __bfloat162float(hi));
            }
        }
    } else {
        const int ru8 = g_r_u8;
        const unsigned char* r8 = (const unsigned char*)resets;
        const int* r32 = (const int*)resets;
        for (int idx = threadIdx.x + (bid - 17408) * blockDim.x; idx < HH * BB;
             idx += 32 * blockDim.x) {
            int b = idx >> 9, k = idx & 511;
            bool rs = ru8 ? (r8[b] != 0) : (r32[b] != 0);
            float hv = rs ? 0.0f : h0[b * HH + k];
            __nv_bfloat16 hi = __float2bfloat16(hv);
            g_hb[0][0][idx] = hi;
            g_hb[0][1][idx] = __float2bfloat16(hv - __bfloat162float(hi));
        }
    }
}

// ---------------- kernel 3: zx = x @ Wi  (bf16 3-split tensor-core GEMM) ----------------
#define AROW 24
#define BROW 136

#define LOAD_STAGE(buf, ks) do {                                                           \
    const int kb_ = (ks) * 16;                                                             \
    _Pragma("unroll")                                                                      \
    for (int j_ = 0; j_ < 4; ++j_) {                                                       \
        int id_ = tid + 256 * j_;                                                          \
        if (id_ < 512) {                                                                   \
            int plane_ = id_ >> 8; int r_ = id_ & 255; int row_ = r_ >> 1; int half_ = r_ & 1; \
            const __nv_bfloat16* src_ = (plane_ ? g_xlo : g_xhi)                           \
                + (size_t)(mbase + row_) * HH + kb_ + half_ * 8;                           \
            uint32_t dst_ = Abase + (((buf) * 2 + plane_) * 128 * AROW + row_ * AROW + half_ * 8) * 2; \
            cpa16(dst_, src_);                                                             \
        } else {                                                                           \
            int id2_ = id_ - 512; int plane_ = id2_ >> 8; int r_ = id2_ & 255;             \
            int krow_ = r_ >> 4; int seg_ = r_ & 15;                                       \
            const __nv_bfloat16* src_ = (plane_ ? g_wlo : g_whi)                           \
                + (size_t)(kb_ + krow_) * NN + nbase + seg_ * 8;                           \
            uint32_t dst_ = Bbase + (((buf) * 2 + plane_) * 16 * BROW + krow_ * BROW + seg_ * 8) * 2; \
            cpa16(dst_, src_);                                                             \
        }                                                                                  \
    } } while (0)

__global__ __launch_bounds__(256) void k_mm_pre() {
    __shared__ __align__(128) __nv_bfloat16 Asm[2][2][128 * AROW];
    __shared__ __align__(128) __nv_bfloat16 Bsm[2][2][16 * BROW];
    const int tid = threadIdx.x;
    const int nbase = blockIdx.x * 128;
    const int mbase = blockIdx.y * 128;
    const int wid = tid >> 5, lane = tid & 31;
    const int wm = wid & 1, wn = wid >> 1;

    uint32_t Abase = (uint32_t)__cvta_generic_to_shared(&Asm[0][0][0]);
    uint32_t Bbase = (uint32_t)__cvta_generic_to_shared(&Bsm[0][0][0]);

    const int gid = lane >> 2, tig = lane & 3;
    const int arow = (lane & 7) + 8 * ((lane >> 3) & 1);
    const int acol = (lane >> 4) * 8;
    const int bk = lane & 15;

    float c[4][4][4] = {};

    LOAD_STAGE(0, 0);
    CP_COMMIT();

    #pragma unroll 1
    for (int ks = 0; ks < 32; ++ks) {
        const int buf = ks & 1;
        if (ks < 31) {
            LOAD_STAGE((ks + 1) & 1, ks + 1);
            CP_COMMIT();
            CP_WAIT(1);
        } else {
            CP_WAIT(0);
        }
        __syncthreads();

        uint32_t a_hi[4][4], a_lo[4][4];
        #pragma unroll
        for (int mi = 0; mi < 4; ++mi) {
            int rowoff = wm * 64 + mi * 16 + arow;
            uint32_t ah = Abase + ((buf * 2 + 0) * 128 * AROW + rowoff * AROW + acol) * 2;
            uint32_t al = Abase + ((buf * 2 + 1) * 128 * AROW + rowoff * AROW + acol) * 2;
            LDSM4(a_hi[mi], ah);
            LDSM4(a_lo[mi], al);
        }
        uint32_t bhf[4][2], blf[4][2];
        #pragma unroll
        for (int ni = 0; ni < 4; ++ni) {
            int n0 = wn * 32 + ni * 8;
            uint32_t bh = Bbase + ((buf * 2 + 0) * 16 * BROW + bk * BROW + n0) * 2;
            uint32_t bl = Bbase + ((buf * 2 + 1) * 16 * BROW + bk * BROW + n0) * 2;
            LDSM2T(bhf[ni], bh);
            LDSM2T(blf[ni], bl);
        }
        #pragma unroll
        for (int mi = 0; mi < 4; ++mi)
            #pragma unroll
            for (int ni = 0; ni < 4; ++ni) {
                MMA_BF16(c[mi][ni], a_hi[mi], bhf[ni]);
                MMA_BF16(c[mi][ni], a_hi[mi], blf[ni]);
                MMA_BF16(c[mi][ni], a_lo[mi], bhf[ni]);
            }
        __syncthreads();
    }

    #pragma unroll
    for (int mi = 0; mi < 4; ++mi)
        #pragma unroll
        for (int ni = 0; ni < 4; ++ni) {
            int m0 = mbase + wm * 64 + mi * 16 + gid;
            int n = nbase + wn * 32 + ni * 8 + tig * 2;
            *(float2*)(g_zx + (size_t)m0 * NN + n) = make_float2(c[mi][ni][0], c[mi][ni][1]);
            *(float2*)(g_zx + (size_t)(m0 + 8) * NN + n) = make_float2(c[mi][ni][2], c[mi][ni][3]);
        }
}

// ---------------- kernel 4: persistent scanned-LSTM, 4 independent batch groups ----------------
// Group g = cta>>5 owns batch rows [16g,16g+16). CTA lc = cta&31 owns state cols
// [16lc,16lc+16) -> 64 z-cols. Warps K-split 8x64: warp w's producers = CTAs
// (grp, 4w..4w+4), ALL 8 warps each -> 32 per-WARP flags, one polled per lane.
// Publish is PER WARP: warp w stores h rows {2w,2w+1} (its epilogue threads),
// __syncwarp, lane0 st.release. Buffer safety: h[t+1] writes happen after the
// zs __syncthreads, which joins all 8 warps' polls (>= t over all 32 CTAs x 8
// warps); warp-flag >= t implies that warp already staged h[t-1].
#define HROW 520                          // bf16 per SMEM h row (1040 B)
#define HPLANE (GB * HROW)                // one plane (16 rows)
#define HSM_BYTES (2 * HPLANE * 2)        // 33280
#define ZSP 80                            // floats per zs row (conflict-free)
#define SMEM_TOTAL (HSM_BYTES + 8 * GB * ZSP * 4)   // 74240

__global__ __launch_bounds__(256, 1)
void lstm_main(const float* __restrict__ Wh, const float* __restrict__ bias,
               const float* __restrict__ c0, const void* __restrict__ resets,
               float* __restrict__ ys) {
    extern __shared__ __align__(128) char smem[];
    __nv_bfloat16* hsm = (__nv_bfloat16*)smem;          // [2 planes][16][HROW]
    float* zsb = (float*)(smem + HSM_BYTES);            // [8][16][ZSP]
    const uint32_t hb32 = (uint32_t)__cvta_generic_to_shared(hsm);

    const int tid = threadIdx.x;
    const int cta = blockIdx.x;
    const int grp = cta >> 5;          // 0..3
    const int lc  = cta & 31;          // 0..31
    const int wid = tid >> 5, lane = tid & 31;
    const int gid = lane >> 2, tig = lane & 3;
    const int wk = wid * 64;

    const int srow = lane & 15, schunk = lane >> 4;      // stage identity
    const int arow = (lane & 7) + 8 * ((lane >> 3) & 1); // ldmatrix identity
    const int acol = (lane >> 4) * 8;

    // producer warp-flag polled by this lane: CTA grp*32 + 4*wid + (lane>>3), warp lane&7
    const int* pollflag =
        g_flag + ((((grp * GCTAS + wid * 4 + (lane >> 3)) << 3) + (lane & 7)) << 5);
    // this warp's own publish flag
    int* wflag = g_flag + ((((cta) << 3) + wid) << 5);

    // ---- build register-resident B fragments from fp32 Wh (once) ----
    unsigned bh[8][4][2], bl[8][4][2];
    #pragma unroll
    for (int nt = 0; nt < 8; ++nt) {
        const int n = nt * 8 + gid;                       // 0..63
        const int gcol = (n >> 4) * 512 + lc * 16 + (n & 15);
        #pragma unroll
        for (int kt = 0; kt < 4; ++kt) {
            const int k0 = wk + kt * 16 + 2 * tig;
            float f0 = Wh[(size_t)k0 * NN + gcol];
            float f1 = Wh[(size_t)(k0 + 1) * NN + gcol];
            float f2 = Wh[(size_t)(k0 + 8) * NN + gcol];
            float f3 = Wh[(size_t)(k0 + 9) * NN + gcol];
            float h0f = __bfloat162float(__float2bfloat16(f0));
            float h1f = __bfloat162float(__float2bfloat16(f1));
            float h2f = __bfloat162float(__float2bfloat16(f2));
            float h3f = __bfloat162float(__float2bfloat16(f3));
            bh[nt][kt][0] = packbf(h0f, h1f);
            bh[nt][kt][1] = packbf(h2f, h3f);
            bl[nt][kt][0] = packbf(f0 - h0f, f1 - h1f);
            bl[nt][kt][1] = packbf(f2 - h2f, f3 - h3f);
        }
    }

    // ---- epilogue identity: one (local b, local j) element; warp w owns rows 2w,2w+1 ----
    const int eb = tid >> 4;           // 0..15 local batch row
    const int ej = tid & 15;           // 0..15 local state col
    const int gb = grp * GB + eb;      // global batch row
    const int jcol = lc * 16 + ej;     // global state col
    float c = c0[gb * HH + jcol];
    const float bi = bias[jcol];
    const float bf = bias[512 + jcol];
    const float bg = bias[1024 + jcol];
    const float bo = bias[1536 + jcol];
    const int ru8 = g_r_u8;
    const unsigned char* r8 = (const unsigned char*)resets;
    const int* r32 = (const int*)resets;

    for (int t = 0; t < TT; ++t) {
        // prefetches (DRAM / L2) — issued before the flag wait to hide latency
        const float* zxr = g_zx + (size_t)(t * BB + gb) * NN + jcol;
        float z0 = __ldcg(zxr);
        float z1 = __ldcg(zxr + 512);
        float z2 = __ldcg(zxr + 1024);
        float z3 = __ldcg(zxr + 1536);
        bool rs  = ru8 ? (__ldg(r8 + t * BB + gb) != 0) : (__ldg(r32 + t * BB + gb) != 0);
        bool rs2 = false;
        if (t + 1 < TT)
            rs2 = ru8 ? (__ldg(r8 + (t + 1) * BB + gb) != 0)
                      : (__ldg(r32 + (t + 1) * BB + gb) != 0);

        // ---- dependency wait: 32 producer warps (4 CTAs x 8 warps) published h[t] ----
        if (t > 0) {
            int v = ld_acq(pollflag);
            unsigned ok = __ballot_sync(0xffffffffu, v >= t);
            while (ok != 0xffffffffu) {
                __nanosleep(32);
                v = ld_acq(pollflag);
                ok = __ballot_sync(0xffffffffu, v >= t);
            }
        }

        const __nv_bfloat16* hhi = g_hb[t & 1][0] + (size_t)grp * GB * HH;
        const __nv_bfloat16* hlo = g_hb[t & 1][1] + (size_t)grp * GB * HH;

        // ---- stage this warp's k-slice (16 rows x 64 k, 2 planes), 2 pipelined halves ----
        #pragma unroll
        for (int hh = 0; hh < 2; ++hh) {
            #pragma unroll
            for (int i = 0; i < 2; ++i) {
                const int k0 = wk + (hh * 4 + schunk + 2 * i) * 8;
                cpa16(hb32 + (srow * HROW + k0) * 2, hhi + srow * HH + k0);
                cpa16(hb32 + (HPLANE + srow * HROW + k0) * 2, hlo + srow * HH + k0);
            }
            CP_COMMIT();
        }

        float acc[8][4];
        #pragma unroll
        for (int nt = 0; nt < 8; ++nt)
            #pragma unroll
            for (int q = 0; q < 4; ++q) acc[nt][q] = 0.0f;

        CP_WAIT(1);   // half 0 (kt 0,1) resident
        #pragma unroll
        for (int kt = 0; kt < 4; ++kt) {
            if (kt == 2) CP_WAIT(0);   // half 1 resident
            unsigned ahi[4], alo[4];
            {
                const uint32_t col = (uint32_t)(wk + kt * 16 + acol);
                uint32_t ah = hb32 + (arow * HROW + col) * 2;
                uint32_t al = ah + HPLANE * 2;
                LDSM4(ahi, ah);
                LDSM4(alo, al);
            }
            #pragma unroll
            for (int nt = 0; nt < 8; ++nt) {
                MMA_BF16(acc[nt], ahi, bh[nt][kt]);
                MMA_BF16(acc[nt], ahi, bl[nt][kt]);
                MMA_BF16(acc[nt], alo, bh[nt][kt]);
            }
        }

        // write K-split partials: zs[wid][row][ncol]
        #pragma unroll
        for (int nt = 0; nt < 8; ++nt) {
            const int col = nt * 8 + 2 * tig;
            *(float2*)&zsb[(wid * GB + gid) * ZSP + col] = make_float2(acc[nt][0], acc[nt][1]);
            *(float2*)&zsb[(wid * GB + gid + 8) * ZSP + col] = make_float2(acc[nt][2], acc[nt][3]);
        }
        __syncthreads();   // joins all warps: CTA-wide knowledge "all producers >= t"

        // ---- epilogue: gates, state update, h store, per-warp publish, ys store ----
        {
            float zi = z0 + bi, zf = z1 + bf, zg = z2 + bg, zo = z3 + bo;
            #pragma unroll
            for (int s = 0; s < 8; ++s) {
                const float* zr = zsb + (s * GB + eb) * ZSP;
                zi += zr[ej];
                zf += zr[16 + ej];
                zg += zr[32 + ej];
                zo += zr[48 + ej];
            }

            if (rs) c = 0.0f;

            float iv = sigf(zi);
            float fv = sigf(zf);
            float gv = tanhf(zg);
            float ov = sigf(zo);
            float ncr = fv * c + iv * gv;
            float nh = ov * tanhf(ncr);
            c = clampf1(ncr);
            float nhc = clampf1(nh);

            if (t + 1 < TT) {
                float hv = rs2 ? 0.0f : nhc;
                __nv_bfloat16 hi = __float2bfloat16(hv);
                const int nb = (t + 1) & 1;
                g_hb[nb][0][gb * HH + jcol] = hi;
                g_hb[nb][1][gb * HH + jcol] = __float2bfloat16(hv - __bfloat162float(hi));
                __syncwarp();
                if (lane == 0) st_rel(wflag, t + 1);   // cumulative release after syncwarp
            }

            ys[(size_t)t * BB * HH + (size_t)gb * HH + jcol] = nhc;
        }
    }
}

// ---------------- launch ----------------
extern "C" void kernel_launch(void* const* d_in, const int* in_sizes, int n_in,
                              void* d_out, int out_size) {
    const float* xs     = (const float*)d_in[0];
    const void*  resets = d_in[1];
    const float* c0     = (const float*)d_in[2];
    const float* h0     = (const float*)d_in[3];
    const float* Wi     = (const float*)d_in[4];
    const float* Wh     = (const float*)d_in[5];
    const float* bias   = (const float*)d_in[6];
    float* ys = (float*)d_out;

    cudaFuncSetAttribute(lstm_main, cudaFuncAttributeMaxDynamicSharedMemorySize, SMEM_TOTAL);

    k_detect<<<1, 256>>>((const unsigned char*)resets);
    k_prep<<<17440, 256>>>(xs, Wi, h0, resets);
    dim3 gpre(16, 256);
    k_mm_pre<<<gpre, 256>>>();
    lstm_main<<<128, 256, SMEM_TOTAL>>>(Wh, bias, c0, resets, ys);
}